// round 14
// baseline (speedup 1.0000x reference)
#include <cuda_runtime.h>

#define BSZ   1024
#define TLEN  64
#define SDIM  30
#define DDIM  200
#define HDIM  200
#define EDIM  1024
#define ADIM  6

// padded row strides (floats) to keep lane-pair LDS conflict-free
#define ROWP  204     // activation rows (200 data + 4 pad); 4*204 % 32 == 16
#define INP   44      // s_in rows (36 data + pad); 4*44 % 32 == 16

typedef unsigned long long ull;

// ---------------------------------------------------------------------------
// Device scratch
// ---------------------------------------------------------------------------
__device__ float g_eo[(size_t)BSZ * TLEN * HDIM];   // embed @ w_obs1[200:] + b_obs1

// k-quad packed weights (float4 = 4 consecutive k values for one output col)
__device__ float4 g_gru4[6 * 50 * 200];  // [st][kq][c]; st: Wz,Wr,Wh,Uz,Ur,Uh
__device__ float4 g_p4[2 * 50 * 200];    // [mat][kq][c]; mat: img2, obs1d
__device__ float4 g_i14[9 * 200];        // img1 [kq][c], K=36
__device__ float4 g_h4[4 * 50 * 30];     // heads [h][kq][s]
// eo weights, k-pair interleaved: float idx ((kp*200 + c)*2 + p), kp 0..511
__device__ ull    g_wep[102400];

// ---------------------------------------------------------------------------
// Helpers
// ---------------------------------------------------------------------------
__device__ __forceinline__ ull fma2(ull a, ull b, ull c) {
    ull d;
    asm("fma.rn.f32x2 %0, %1, %2, %3;" : "=l"(d) : "l"(a), "l"(b), "l"(c));
    return d;
}
__device__ __forceinline__ float sum2(ull a) {
    float2 f;
    asm("mov.b64 {%0, %1}, %2;" : "=f"(f.x), "=f"(f.y) : "l"(a));
    return f.x + f.y;
}
__device__ __forceinline__ ulonglong2 ldg2(const float4* p) {
    return __ldg(reinterpret_cast<const ulonglong2*>(p));
}
__device__ __forceinline__ ulonglong2 lds2(const float* p) {
    return *reinterpret_cast<const ulonglong2*>(p);
}
__device__ __forceinline__ float rcpa(float x) {
    float r;
    asm("rcp.approx.f32 %0, %1;" : "=f"(r) : "f"(x));
    return r;
}
__device__ __forceinline__ float elu1(float v) {
    return v > 0.f ? v : (__expf(v) - 1.f);
}
__device__ __forceinline__ float softplus1(float x) {
    return fmaxf(x, 0.f) + __logf(1.f + __expf(-fabsf(x)));
}
__device__ __forceinline__ float sigmoid1(float x) {
    return rcpa(1.f + __expf(-x));
}
__device__ __forceinline__ void cp16(void* s, const void* g) {
    unsigned ss = (unsigned)__cvta_generic_to_shared(s);
    asm volatile("cp.async.ca.shared.global [%0], [%1], 16;" :: "r"(ss), "l"(g) : "memory");
}
#define CP_COMMIT() asm volatile("cp.async.commit_group;" ::: "memory")
#define CP_WAIT1()  asm volatile("cp.async.wait_group 1;" ::: "memory")
#define CP_WAIT0()  asm volatile("cp.async.wait_group 0;" ::: "memory")

// ---------------------------------------------------------------------------
// Repack kernel: k-quad layouts + g_wep
// ---------------------------------------------------------------------------
__global__ void repack_kernel(const float* __restrict__ w_img1,
                              const float* __restrict__ gru_w,
                              const float* __restrict__ gru_u,
                              const float* __restrict__ w_img2,
                              const float* __restrict__ w_obs1,
                              const float* __restrict__ w_omean,
                              const float* __restrict__ w_ostd,
                              const float* __restrict__ w_imean,
                              const float* __restrict__ w_istd) {
    int i = blockIdx.x * 256 + threadIdx.x;
    if (i < 240000) {                       // GRU 6 streams
        int f = i & 3, q = i >> 2;
        int st = q / 10000, rem = q % 10000, kq = rem / 200, cc = rem % 200;
        int k = 4 * kq + f;
        float v = (st < 3) ? gru_w[k * 600 + st * 200 + cc]
                           : gru_u[k * 600 + (st - 3) * 200 + cc];
        ((float*)g_gru4)[i] = v;
    } else if (i < 320000) {                // img2 / obs1d
        int j = i - 240000;
        int f = j & 3, q = j >> 2;
        int mat = q / 10000, rem = q % 10000, kq = rem / 200, cc = rem % 200;
        int k = 4 * kq + f;
        ((float*)g_p4)[j] = (mat == 0) ? w_img2[k * 200 + cc] : w_obs1[k * 200 + cc];
    } else if (i < 327200) {                // img1
        int j = i - 320000;
        int f = j & 3, q = j >> 2;
        int kq = q / 200, cc = q % 200;
        int k = 4 * kq + f;
        ((float*)g_i14)[j] = w_img1[k * 200 + cc];
    } else if (i < 351200) {                // heads
        int j = i - 327200;
        int f = j & 3, q = j >> 2;
        int h = q / 1500, rem = q % 1500, kq = rem / 30, s = rem % 30;
        int k = 4 * kq + f;
        const float* src = (h == 0) ? w_omean : (h == 1) ? w_ostd
                         : (h == 2) ? w_imean : w_istd;
        ((float*)g_h4)[j] = src[k * 30 + s];
    } else if (i < 556000) {                // eo weights (embed rows of w_obs1)
        int j = i - 351200;                 // (kp*200+c)*2 + p
        int p = j & 1, q = j >> 1;
        int c = q % 200, kp = q / 200;
        ((float*)g_wep)[j] = w_obs1[(size_t)(200 + 2 * kp + p) * 200 + c];
    }
}

// ---------------------------------------------------------------------------
// Kernel 1: eo GEMM, cp.async 3-stage pipeline, ONE sync per chunk.
// ---------------------------------------------------------------------------
__global__ __launch_bounds__(320, 1)
void eo_gemm_kernel(const float* __restrict__ embed,
                    const float* __restrict__ b_obs1) {
    __shared__ __align__(16) float sbuf[3 * 8448];

    const int tid = threadIdx.x;
    const int tx = tid % 40;
    const int ty = tid / 40;
    const int m0 = blockIdx.x * 64;

    ull acc[8][5];
#pragma unroll
    for (int r = 0; r < 8; r++)
#pragma unroll
        for (int j = 0; j < 5; j++) acc[r][j] = 0ull;

    auto issue_chunk = [&](int cc) {
        const int k0 = cc * 32;
        float* dst = sbuf + (cc % 3) * 8448;
        for (int i = tid; i < 512; i += 320) {
            int r = i >> 3, q = i & 7;
            cp16(dst + r * 32 + q * 4,
                 embed + (size_t)(m0 + r) * 1024 + k0 + q * 4);
        }
        const float* wsrc = (const float*)g_wep + (size_t)(k0 >> 1) * 400;
        float* wdst = dst + 2048;
        for (int i = tid; i < 1600; i += 320) {
            cp16(wdst + i * 4, wsrc + i * 4);
        }
        CP_COMMIT();
    };

    issue_chunk(0);
    issue_chunk(1);

    for (int c = 0; c < 32; c++) {
        if (c < 31) { CP_WAIT1(); } else { CP_WAIT0(); }
        // Single barrier per chunk: also orders buffer (c+2)%3 reuse, since all
        // threads passing this sync completed iteration c-1's compute on it.
        __syncthreads();
        if (c + 2 < 32) issue_chunk(c + 2);

        const float* bs = sbuf + (c % 3) * 8448;
        const ull* as_u = (const ull*)bs;
        const ull* ws_u = (const ull*)(bs + 2048);
#pragma unroll
        for (int kp = 0; kp < 16; kp++) {
            ull wv[5];
#pragma unroll
            for (int j = 0; j < 5; j++) wv[j] = ws_u[kp * 200 + tx * 5 + j];
#pragma unroll
            for (int r = 0; r < 8; r++) {
                ull av = as_u[(ty * 8 + r) * 16 + kp];
#pragma unroll
                for (int j = 0; j < 5; j++) acc[r][j] = fma2(av, wv[j], acc[r][j]);
            }
        }
    }

#pragma unroll
    for (int r = 0; r < 8; r++) {
        int m = m0 + ty * 8 + r;
#pragma unroll
        for (int j = 0; j < 5; j++) {
            int cc = tx * 5 + j;
            g_eo[(size_t)m * 200 + cc] = sum2(acc[r][j]) + b_obs1[cc];
        }
    }
}

// ---------------------------------------------------------------------------
// Kernel 2: persistent recurrent kernel, lane-pair twinning + cross-barrier
// weight prefetch (phase-entry LDG latency overlapped with preceding phase).
// 128 CTAs x 8 rows, 800 threads, 5 barriers/step.
// ---------------------------------------------------------------------------
__global__ __launch_bounds__(800, 1)
void rssm_recur_kernel(const float* __restrict__ action,
                       const float* __restrict__ noise_prior,
                       const float* __restrict__ noise_post,
                       const float* __restrict__ b_img1,
                       const float* __restrict__ gru_b,
                       const float* __restrict__ gru_rb,
                       const float* __restrict__ b_img2,
                       const float* __restrict__ b_imean,
                       const float* __restrict__ b_istd,
                       const float* __restrict__ b_omean,
                       const float* __restrict__ b_ostd,
                       float* __restrict__ out) {
    __shared__ __align__(16) float sm[15128];
    float* s_in = sm;             // [8][INP]                              352
    float* det0 = sm + 352;       // [8][ROWP]                            1632
    float* det1 = sm + 1984;      // [8][ROWP]
    float* s_x  = sm + 3616;      // [8][ROWP]  img1 out, later x2
    float* s_xo = sm + 5248;      // [8][ROWP]
    float* s_eo = sm + 6880;      // [8][ROWP]
    float* s_g  = sm + 8512;      // [3][8][ROWP] d-side GRU partials     4896
    float* s_b1 = sm + 13408;     // [200]
    float* s_b2 = sm + 13608;     // [200]
    float* s_gb = sm + 13808;     // [6][200]
    float* s_hb = sm + 15008;     // [4][30]

    const int tid = threadIdx.x;
    const int b0 = blockIdx.x * 8;

    // ---- P2 mapping: (side, c, rh) with rh in the lane LSB ----
    const int sgP = tid / 400;            // 0: x-side, 1: d-side
    const int cP  = (tid % 400) >> 1;     // 0..199
    const int rhP = tid & 1;              // row half
    const float4* wpP2 = g_gru4 + sgP * 30000 + cP;

    // ---- P4 mapping ----
    const int matP4 = tid / 400;
    const int cP4   = (tid % 400) >> 1;
    const int rhP4  = tid & 1;
    const float4* wpP4 = g_p4 + matP4 * 10000 + cP4;

    // ---- P5 mapping (tid < 480): pair p (0=post,1=prior), row r, col s ----
    const int pP5 = tid / 240;
    const int remP5 = tid % 240;
    const int rP5 = remP5 / 30;
    const int sP5 = remP5 % 30;
    const float* nptr = (pP5 ? noise_prior : noise_post)
                        + (size_t)(b0 + rP5) * SDIM + sP5;
    float* optr = out + (size_t)(b0 + rP5) * TLEN * 580 + (pP5 ? 290 : 0) + sP5;
    const float4* wmP5 = g_h4 + (2 * pP5) * 1500 + sP5;
    const float4* wsP5 = g_h4 + (2 * pP5 + 1) * 1500 + sP5;

    // ---- init: biases to smem, carry zeros, action[0] ----
    if (tid < 200) {
        s_b1[tid] = b_img1[tid];
        s_b2[tid] = b_img2[tid];
    }
    for (int i = tid; i < 1200; i += 800) {
        int st = i / 200, cc = i % 200;
        s_gb[i] = (st < 3) ? gru_b[st * 200 + cc] : gru_rb[(st - 3) * 200 + cc];
    }
    if (tid < 120) {
        int h = tid / 30, s = tid % 30;
        s_hb[tid] = (h == 0) ? b_omean[s] : (h == 1) ? b_ostd[s]
                  : (h == 2) ? b_imean[s] : b_istd[s];
    }
    for (int i = tid; i < 8 * INP; i += 800) s_in[i] = 0.f;
    for (int i = tid; i < 8 * ROWP; i += 800) det0[i] = 0.f;
    if (tid < 48) {
        int r = tid / 6, j = tid % 6;
        s_in[r * INP + 30 + j] = action[(size_t)(b0 + r) * (TLEN * ADIM) + j];
    }
    float* pd = det0;
    float* pn = det1;
    __syncthreads();

    for (int t = 0; t < TLEN; ++t) {
        // ---- prefetch P2's first weight trio (independent of P1) ----------
        ulonglong2 w0 = ldg2(wpP2);
        ulonglong2 w1 = ldg2(wpP2 + 10000);
        ulonglong2 w2 = ldg2(wpP2 + 20000);

        // ====== P1: x = elu([stoch,action]@W1 + b)  |  eo loads =============
        if (tid < 400) {
            const int c = tid >> 1, rh = tid & 1;
            ull acc[4];
#pragma unroll
            for (int j = 0; j < 4; j++) acc[j] = 0ull;
#pragma unroll
            for (int kq = 0; kq < 9; kq++) {
                ulonglong2 w = ldg2(g_i14 + kq * 200 + c);
#pragma unroll
                for (int j = 0; j < 4; j++) {
                    ulonglong2 v = lds2(s_in + (rh * 4 + j) * INP + 4 * kq);
                    acc[j] = fma2(v.x, w.x, acc[j]);
                    acc[j] = fma2(v.y, w.y, acc[j]);
                }
            }
            float bb = s_b1[c];
#pragma unroll
            for (int j = 0; j < 4; j++)
                s_x[(rh * 4 + j) * ROWP + c] = elu1(sum2(acc[j]) + bb);
        } else if (tid >= 600) {
            int t2 = tid - 600;
#pragma unroll
            for (int i = 0; i < 8; i++) {
                s_eo[i * ROWP + t2] =
                    __ldg(&g_eo[((size_t)(b0 + i) * TLEN + t) * 200 + t2]);
            }
        }
        __syncthreads();

        // ====== P2: 3 streams x 1 col x 4 rows, twinned lanes ===============
        float xz[4], xr[4], xh[4];   // x-side results (sgP==0 only)
        {
            const float* src = sgP ? pd : s_x;
            const float* srb = src + rhP * 4 * ROWP;
            ull a0[4], a1[4], a2[4];
#pragma unroll
            for (int j = 0; j < 4; j++) { a0[j] = 0; a1[j] = 0; a2[j] = 0; }
            for (int kq = 0; kq < 50; kq++) {
                const int kn = (kq < 49) ? kq + 1 : 49;
                ulonglong2 n0 = ldg2(wpP2 + kn * 200);
                ulonglong2 n1 = ldg2(wpP2 + 10000 + kn * 200);
                ulonglong2 n2 = ldg2(wpP2 + 20000 + kn * 200);
#pragma unroll
                for (int j = 0; j < 4; j++) {
                    ulonglong2 v = lds2(srb + j * ROWP + 4 * kq);
                    a0[j] = fma2(v.x, w0.x, a0[j]);
                    a0[j] = fma2(v.y, w0.y, a0[j]);
                    a1[j] = fma2(v.x, w1.x, a1[j]);
                    a1[j] = fma2(v.y, w1.y, a1[j]);
                    a2[j] = fma2(v.x, w2.x, a2[j]);
                    a2[j] = fma2(v.y, w2.y, a2[j]);
                }
                w0 = n0; w1 = n1; w2 = n2;
            }
            if (sgP) {
#pragma unroll
                for (int j = 0; j < 4; j++) {
                    int row = rhP * 4 + j;
                    s_g[row * ROWP + cP]            = sum2(a0[j]) + s_gb[600 + cP];
                    s_g[1632 + row * ROWP + cP]     = sum2(a1[j]) + s_gb[800 + cP];
                    s_g[3264 + row * ROWP + cP]     = sum2(a2[j]) + s_gb[1000 + cP];
                }
            } else {
#pragma unroll
                for (int j = 0; j < 4; j++) {
                    xz[j] = sum2(a0[j]) + s_gb[cP];
                    xr[j] = sum2(a1[j]) + s_gb[200 + cP];
                    xh[j] = sum2(a2[j]) + s_gb[400 + cP];
                }
            }
        }
        __syncthreads();

        // ---- prefetch P4's first weight (independent of P3) ---------------
        ulonglong2 w4 = ldg2(wpP4);

        // ====== P3: gates, deter_n (x-side threads own it) ==================
        if (tid < 400) {
#pragma unroll
            for (int j = 0; j < 4; j++) {
                int row = rhP * 4 + j;
                int idx = row * ROWP + cP;
                float z  = sigmoid1(xz[j] + s_g[idx]);
                float rg = sigmoid1(xr[j] + s_g[1632 + idx]);
                float a  = xh[j] + rg * s_g[3264 + idx];
                float e2 = __expf(2.f * a);
                float th = 1.f - 2.f * rcpa(e2 + 1.f);
                float dn = z * pd[idx] + (1.f - z) * th;
                pn[idx] = dn;
                float* orow = out + ((size_t)(b0 + row) * TLEN + t) * 580;
                orow[90 + cP]  = dn;
                orow[380 + cP] = dn;
            }
        }
        __syncthreads();

        // ====== P4: x2 / xo, 1 col x 4 rows, twinned lanes ==================
        {
            const float* db = pn + rhP4 * 4 * ROWP;
            ull acc[4];
#pragma unroll
            for (int j = 0; j < 4; j++) acc[j] = 0ull;
            for (int kq = 0; kq < 50; kq++) {
                const int kn = (kq < 49) ? kq + 1 : 49;
                ulonglong2 n = ldg2(wpP4 + kn * 200);
#pragma unroll
                for (int j = 0; j < 4; j++) {
                    ulonglong2 v = lds2(db + j * ROWP + 4 * kq);
                    acc[j] = fma2(v.x, w4.x, acc[j]);
                    acc[j] = fma2(v.y, w4.y, acc[j]);
                }
                w4 = n;
            }
            if (matP4 == 0) {
                float bb = s_b2[cP4];
#pragma unroll
                for (int j = 0; j < 4; j++) {
                    int row = rhP4 * 4 + j;
                    s_x[row * ROWP + cP4] = elu1(sum2(acc[j]) + bb);
                }
            } else {
#pragma unroll
                for (int j = 0; j < 4; j++) {
                    int row = rhP4 * 4 + j;
                    s_xo[row * ROWP + cP4] = elu1(sum2(acc[j]) + s_eo[row * ROWP + cP4]);
                }
            }
        }

        // ---- prefetch P5's first weights + noise (independent of P4 sync) --
        ulonglong2 m0, s0;
        float nz = 0.f;
        if (tid < 480) {
            m0 = ldg2(wmP5);
            s0 = ldg2(wsP5);
            nz = __ldg(nptr + (size_t)t * (BSZ * SDIM));
        }
        __syncthreads();

        // ====== P5: heads + samples fused (480 thr) + action prefetch =======
        if (tid < 480) {
            const float* srcr = (pP5 ? s_x : s_xo) + rP5 * ROWP;
            ull am = 0ull, as = 0ull;
            for (int kq = 0; kq < 50; kq++) {
                int kn = (kq < 49) ? kq + 1 : 49;
                ulonglong2 mn = ldg2(wmP5 + kn * 30);
                ulonglong2 sn = ldg2(wsP5 + kn * 30);
                ulonglong2 v = lds2(srcr + 4 * kq);
                am = fma2(v.x, m0.x, am);
                am = fma2(v.y, m0.y, am);
                as = fma2(v.x, s0.x, as);
                as = fma2(v.y, s0.y, as);
                m0 = mn; s0 = sn;
            }
            float mean = sum2(am) + s_hb[2 * pP5 * 30 + sP5];
            float sdev = softplus1(sum2(as) + s_hb[(2 * pP5 + 1) * 30 + sP5]);
            if (pP5) sdev += 0.1f;
            float stoch = mean + sdev * nz;

            float* op = optr + (size_t)t * 580;
            op[0]  = mean;
            op[30] = sdev;
            op[60] = stoch;
            if (pP5 == 0) s_in[rP5 * INP + sP5] = stoch;  // posterior carry
        } else if (tid >= 752 && t + 1 < TLEN) {
            int idx = tid - 752;
            int r = idx / 6, j = idx % 6;
            s_in[r * INP + 30 + j] =
                action[(size_t)(b0 + r) * (TLEN * ADIM) + (t + 1) * ADIM + j];
        }

        { float* tmp = pd; pd = pn; pn = tmp; }
        __syncthreads();
    }
}

// ---------------------------------------------------------------------------
// Launch
// ---------------------------------------------------------------------------
extern "C" void kernel_launch(void* const* d_in, const int* in_sizes, int n_in,
                              void* d_out, int out_size) {
    const float* embed       = (const float*)d_in[0];
    const float* action      = (const float*)d_in[1];
    const float* noise_prior = (const float*)d_in[2];
    const float* noise_post  = (const float*)d_in[3];
    const float* w_img1      = (const float*)d_in[4];
    const float* b_img1      = (const float*)d_in[5];
    const float* gru_w       = (const float*)d_in[6];
    const float* gru_u       = (const float*)d_in[7];
    const float* gru_b       = (const float*)d_in[8];
    const float* gru_rb      = (const float*)d_in[9];
    const float* w_img2      = (const float*)d_in[10];
    const float* b_img2      = (const float*)d_in[11];
    const float* w_imean     = (const float*)d_in[12];
    const float* b_imean     = (const float*)d_in[13];
    const float* w_istd      = (const float*)d_in[14];
    const float* b_istd      = (const float*)d_in[15];
    const float* w_obs1      = (const float*)d_in[16];
    const float* b_obs1      = (const float*)d_in[17];
    const float* w_omean     = (const float*)d_in[18];
    const float* b_omean     = (const float*)d_in[19];
    const float* w_ostd      = (const float*)d_in[20];
    const float* b_ostd      = (const float*)d_in[21];
    float* out = (float*)d_out;

    repack_kernel<<<(556000 + 255) / 256, 256>>>(w_img1, gru_w, gru_u, w_img2,
                                                 w_obs1, w_omean, w_ostd,
                                                 w_imean, w_istd);
    eo_gemm_kernel<<<BSZ * TLEN / 64, 320>>>(embed, b_obs1);
    rssm_recur_kernel<<<BSZ / 8, 800>>>(action, noise_prior, noise_post,
                                        b_img1, gru_b, gru_rb, b_img2,
                                        b_imean, b_istd, b_omean, b_ostd, out);
}

// round 15
// speedup vs baseline: 1.0686x; 1.0686x over previous
#include <cuda_runtime.h>

#define BSZ   1024
#define TLEN  64
#define SDIM  30
#define DDIM  200
#define HDIM  200
#define EDIM  1024
#define ADIM  6

// padded row strides (floats) to keep lane-pair LDS conflict-free
#define ROWP  204     // activation rows (200 data + 4 pad); 4*204 % 32 == 16
#define INP   44      // s_in rows (36 data + pad); 4*44 % 32 == 16

typedef unsigned long long ull;

// ---------------------------------------------------------------------------
// Device scratch
// ---------------------------------------------------------------------------
__device__ float g_eo[(size_t)BSZ * TLEN * HDIM];   // embed @ w_obs1[200:] + b_obs1

// k-quad packed weights (float4 = 4 consecutive k values for one output col)
__device__ float4 g_gru4[6 * 50 * 200];  // [st][kq][c]; st: Wz,Wr,Wh,Uz,Ur,Uh
__device__ float4 g_p4[2 * 50 * 200];    // [mat][kq][c]; mat: img2, obs1d
__device__ float4 g_i14[9 * 200];        // img1 [kq][c], K=36
__device__ float4 g_h4[4 * 50 * 30];     // heads [h][kq][s]
// eo weights, k-pair interleaved: float idx ((kp*200 + c)*2 + p), kp 0..511
__device__ ull    g_wep[102400];

// ---------------------------------------------------------------------------
// Helpers
// ---------------------------------------------------------------------------
__device__ __forceinline__ ull fma2(ull a, ull b, ull c) {
    ull d;
    asm("fma.rn.f32x2 %0, %1, %2, %3;" : "=l"(d) : "l"(a), "l"(b), "l"(c));
    return d;
}
__device__ __forceinline__ float sum2(ull a) {
    float2 f;
    asm("mov.b64 {%0, %1}, %2;" : "=f"(f.x), "=f"(f.y) : "l"(a));
    return f.x + f.y;
}
__device__ __forceinline__ ulonglong2 ldg2(const float4* p) {
    return __ldg(reinterpret_cast<const ulonglong2*>(p));
}
__device__ __forceinline__ ulonglong2 lds2(const float* p) {
    return *reinterpret_cast<const ulonglong2*>(p);
}
__device__ __forceinline__ float rcpa(float x) {
    float r;
    asm("rcp.approx.f32 %0, %1;" : "=f"(r) : "f"(x));
    return r;
}
__device__ __forceinline__ float elu1(float v) {
    return v > 0.f ? v : (__expf(v) - 1.f);
}
__device__ __forceinline__ float softplus1(float x) {
    return fmaxf(x, 0.f) + __logf(1.f + __expf(-fabsf(x)));
}
__device__ __forceinline__ float sigmoid1(float x) {
    return rcpa(1.f + __expf(-x));
}
__device__ __forceinline__ void cp16(void* s, const void* g) {
    unsigned ss = (unsigned)__cvta_generic_to_shared(s);
    asm volatile("cp.async.ca.shared.global [%0], [%1], 16;" :: "r"(ss), "l"(g) : "memory");
}
#define CP_COMMIT() asm volatile("cp.async.commit_group;" ::: "memory")
#define CP_WAIT1()  asm volatile("cp.async.wait_group 1;" ::: "memory")
#define CP_WAIT0()  asm volatile("cp.async.wait_group 0;" ::: "memory")

// ---------------------------------------------------------------------------
// Repack kernel: k-quad layouts + g_wep
// ---------------------------------------------------------------------------
__global__ void repack_kernel(const float* __restrict__ w_img1,
                              const float* __restrict__ gru_w,
                              const float* __restrict__ gru_u,
                              const float* __restrict__ w_img2,
                              const float* __restrict__ w_obs1,
                              const float* __restrict__ w_omean,
                              const float* __restrict__ w_ostd,
                              const float* __restrict__ w_imean,
                              const float* __restrict__ w_istd) {
    int i = blockIdx.x * 256 + threadIdx.x;
    if (i < 240000) {                       // GRU 6 streams
        int f = i & 3, q = i >> 2;
        int st = q / 10000, rem = q % 10000, kq = rem / 200, cc = rem % 200;
        int k = 4 * kq + f;
        float v = (st < 3) ? gru_w[k * 600 + st * 200 + cc]
                           : gru_u[k * 600 + (st - 3) * 200 + cc];
        ((float*)g_gru4)[i] = v;
    } else if (i < 320000) {                // img2 / obs1d
        int j = i - 240000;
        int f = j & 3, q = j >> 2;
        int mat = q / 10000, rem = q % 10000, kq = rem / 200, cc = rem % 200;
        int k = 4 * kq + f;
        ((float*)g_p4)[j] = (mat == 0) ? w_img2[k * 200 + cc] : w_obs1[k * 200 + cc];
    } else if (i < 327200) {                // img1
        int j = i - 320000;
        int f = j & 3, q = j >> 2;
        int kq = q / 200, cc = q % 200;
        int k = 4 * kq + f;
        ((float*)g_i14)[j] = w_img1[k * 200 + cc];
    } else if (i < 351200) {                // heads
        int j = i - 327200;
        int f = j & 3, q = j >> 2;
        int h = q / 1500, rem = q % 1500, kq = rem / 30, s = rem % 30;
        int k = 4 * kq + f;
        const float* src = (h == 0) ? w_omean : (h == 1) ? w_ostd
                         : (h == 2) ? w_imean : w_istd;
        ((float*)g_h4)[j] = src[k * 30 + s];
    } else if (i < 556000) {                // eo weights (embed rows of w_obs1)
        int j = i - 351200;                 // (kp*200+c)*2 + p
        int p = j & 1, q = j >> 1;
        int c = q % 200, kp = q / 200;
        ((float*)g_wep)[j] = w_obs1[(size_t)(200 + 2 * kp + p) * 200 + c];
    }
}

// ---------------------------------------------------------------------------
// Kernel 1: eo GEMM, cp.async 3-stage pipeline, 640 threads (tile 4x5).
// ---------------------------------------------------------------------------
__global__ __launch_bounds__(640, 1)
void eo_gemm_kernel(const float* __restrict__ embed,
                    const float* __restrict__ b_obs1) {
    __shared__ __align__(16) float sbuf[3 * 8448];

    const int tid = threadIdx.x;
    const int tx = tid % 40;      // 5 cols each
    const int ty = tid / 40;      // 0..15, 4 rows each
    const int m0 = blockIdx.x * 64;

    ull acc[4][5];
#pragma unroll
    for (int r = 0; r < 4; r++)
#pragma unroll
        for (int j = 0; j < 5; j++) acc[r][j] = 0ull;

    auto issue_chunk = [&](int cc) {
        const int k0 = cc * 32;
        float* dst = sbuf + (cc % 3) * 8448;
        if (tid < 512) {
            int r = tid >> 3, q = tid & 7;
            cp16(dst + r * 32 + q * 4,
                 embed + (size_t)(m0 + r) * 1024 + k0 + q * 4);
        }
        const float* wsrc = (const float*)g_wep + (size_t)(k0 >> 1) * 400;
        float* wdst = dst + 2048;
        for (int i = tid; i < 1600; i += 640) {
            cp16(wdst + i * 4, wsrc + i * 4);
        }
        CP_COMMIT();
    };

    issue_chunk(0);
    issue_chunk(1);

    for (int c = 0; c < 32; c++) {
        if (c < 31) { CP_WAIT1(); } else { CP_WAIT0(); }
        __syncthreads();
        if (c + 2 < 32) issue_chunk(c + 2);

        const float* bs = sbuf + (c % 3) * 8448;
        const ull* as_u = (const ull*)bs;
        const ull* ws_u = (const ull*)(bs + 2048);
#pragma unroll
        for (int kp = 0; kp < 16; kp++) {
            ull wv[5];
#pragma unroll
            for (int j = 0; j < 5; j++) wv[j] = ws_u[kp * 200 + tx * 5 + j];
#pragma unroll
            for (int r = 0; r < 4; r++) {
                ull av = as_u[(ty * 4 + r) * 16 + kp];
#pragma unroll
                for (int j = 0; j < 5; j++) acc[r][j] = fma2(av, wv[j], acc[r][j]);
            }
        }
        __syncthreads();
    }

#pragma unroll
    for (int r = 0; r < 4; r++) {
        int m = m0 + ty * 4 + r;
#pragma unroll
        for (int j = 0; j < 5; j++) {
            int cc = tx * 5 + j;
            g_eo[(size_t)m * 200 + cc] = sum2(acc[r][j]) + b_obs1[cc];
        }
    }
}

// ---------------------------------------------------------------------------
// Kernel 2: persistent recurrent kernel (round-13 proven, verbatim).
// 128 CTAs x 8 rows, 800 threads, 5 barriers/step, lane-pair twinning.
// ---------------------------------------------------------------------------
__global__ __launch_bounds__(800, 1)
void rssm_recur_kernel(const float* __restrict__ action,
                       const float* __restrict__ noise_prior,
                       const float* __restrict__ noise_post,
                       const float* __restrict__ b_img1,
                       const float* __restrict__ gru_b,
                       const float* __restrict__ gru_rb,
                       const float* __restrict__ b_img2,
                       const float* __restrict__ b_imean,
                       const float* __restrict__ b_istd,
                       const float* __restrict__ b_omean,
                       const float* __restrict__ b_ostd,
                       float* __restrict__ out) {
    __shared__ __align__(16) float sm[15128];
    float* s_in = sm;             // [8][INP]                              352
    float* det0 = sm + 352;       // [8][ROWP]                            1632
    float* det1 = sm + 1984;      // [8][ROWP]
    float* s_x  = sm + 3616;      // [8][ROWP]  img1 out, later x2
    float* s_xo = sm + 5248;      // [8][ROWP]
    float* s_eo = sm + 6880;      // [8][ROWP]
    float* s_g  = sm + 8512;      // [3][8][ROWP] d-side GRU partials     4896
    float* s_b1 = sm + 13408;     // [200]
    float* s_b2 = sm + 13608;     // [200]
    float* s_gb = sm + 13808;     // [6][200]
    float* s_hb = sm + 15008;     // [4][30]

    const int tid = threadIdx.x;
    const int b0 = blockIdx.x * 8;

    // ---- P2 mapping: (side, c, rh) with rh in the lane LSB ----
    const int sgP = tid / 400;            // 0: x-side, 1: d-side
    const int cP  = (tid % 400) >> 1;     // 0..199
    const int rhP = tid & 1;              // row half
    const float4* wpP2 = g_gru4 + sgP * 30000 + cP;

    // ---- P4 mapping ----
    const int matP4 = tid / 400;
    const int cP4   = (tid % 400) >> 1;
    const int rhP4  = tid & 1;
    const float4* wpP4 = g_p4 + matP4 * 10000 + cP4;

    // ---- P5 mapping (tid < 480): pair p (0=post,1=prior), row r, col s ----
    const int pP5 = tid / 240;
    const int remP5 = tid % 240;
    const int rP5 = remP5 / 30;
    const int sP5 = remP5 % 30;
    const float* nptr = (pP5 ? noise_prior : noise_post)
                        + (size_t)(b0 + rP5) * SDIM + sP5;
    float* optr = out + (size_t)(b0 + rP5) * TLEN * 580 + (pP5 ? 290 : 0) + sP5;
    const float4* wmP5 = g_h4 + (2 * pP5) * 1500 + sP5;
    const float4* wsP5 = g_h4 + (2 * pP5 + 1) * 1500 + sP5;

    // ---- init: biases to smem, carry zeros, action[0] ----
    if (tid < 200) {
        s_b1[tid] = b_img1[tid];
        s_b2[tid] = b_img2[tid];
    }
    for (int i = tid; i < 1200; i += 800) {
        int st = i / 200, cc = i % 200;
        s_gb[i] = (st < 3) ? gru_b[st * 200 + cc] : gru_rb[(st - 3) * 200 + cc];
    }
    if (tid < 120) {
        int h = tid / 30, s = tid % 30;
        s_hb[tid] = (h == 0) ? b_omean[s] : (h == 1) ? b_ostd[s]
                  : (h == 2) ? b_imean[s] : b_istd[s];
    }
    for (int i = tid; i < 8 * INP; i += 800) s_in[i] = 0.f;
    for (int i = tid; i < 8 * ROWP; i += 800) det0[i] = 0.f;
    if (tid < 48) {
        int r = tid / 6, j = tid % 6;
        s_in[r * INP + 30 + j] = action[(size_t)(b0 + r) * (TLEN * ADIM) + j];
    }
    float* pd = det0;
    float* pn = det1;
    __syncthreads();

    for (int t = 0; t < TLEN; ++t) {
        // ====== P1: x = elu([stoch,action]@W1 + b)  |  eo loads =============
        if (tid < 400) {
            const int c = tid >> 1, rh = tid & 1;
            ull acc[4];
#pragma unroll
            for (int j = 0; j < 4; j++) acc[j] = 0ull;
#pragma unroll
            for (int kq = 0; kq < 9; kq++) {
                ulonglong2 w = ldg2(g_i14 + kq * 200 + c);
#pragma unroll
                for (int j = 0; j < 4; j++) {
                    ulonglong2 v = lds2(s_in + (rh * 4 + j) * INP + 4 * kq);
                    acc[j] = fma2(v.x, w.x, acc[j]);
                    acc[j] = fma2(v.y, w.y, acc[j]);
                }
            }
            float bb = s_b1[c];
#pragma unroll
            for (int j = 0; j < 4; j++)
                s_x[(rh * 4 + j) * ROWP + c] = elu1(sum2(acc[j]) + bb);
        } else if (tid >= 600) {
            int t2 = tid - 600;
#pragma unroll
            for (int i = 0; i < 8; i++) {
                s_eo[i * ROWP + t2] =
                    __ldg(&g_eo[((size_t)(b0 + i) * TLEN + t) * 200 + t2]);
            }
        }
        __syncthreads();

        // ====== P2: 3 streams x 1 col x 4 rows, twinned lanes ===============
        float xz[4], xr[4], xh[4];   // x-side results (sgP==0 only)
        {
            const float* src = sgP ? pd : s_x;
            const float* srb = src + rhP * 4 * ROWP;
            ull a0[4], a1[4], a2[4];
#pragma unroll
            for (int j = 0; j < 4; j++) { a0[j] = 0; a1[j] = 0; a2[j] = 0; }
            ulonglong2 w0 = ldg2(wpP2);
            ulonglong2 w1 = ldg2(wpP2 + 10000);
            ulonglong2 w2 = ldg2(wpP2 + 20000);
            for (int kq = 0; kq < 50; kq++) {
                const int kn = (kq < 49) ? kq + 1 : 49;
                ulonglong2 n0 = ldg2(wpP2 + kn * 200);
                ulonglong2 n1 = ldg2(wpP2 + 10000 + kn * 200);
                ulonglong2 n2 = ldg2(wpP2 + 20000 + kn * 200);
#pragma unroll
                for (int j = 0; j < 4; j++) {
                    ulonglong2 v = lds2(srb + j * ROWP + 4 * kq);
                    a0[j] = fma2(v.x, w0.x, a0[j]);
                    a0[j] = fma2(v.y, w0.y, a0[j]);
                    a1[j] = fma2(v.x, w1.x, a1[j]);
                    a1[j] = fma2(v.y, w1.y, a1[j]);
                    a2[j] = fma2(v.x, w2.x, a2[j]);
                    a2[j] = fma2(v.y, w2.y, a2[j]);
                }
                w0 = n0; w1 = n1; w2 = n2;
            }
            if (sgP) {
#pragma unroll
                for (int j = 0; j < 4; j++) {
                    int row = rhP * 4 + j;
                    s_g[row * ROWP + cP]            = sum2(a0[j]) + s_gb[600 + cP];
                    s_g[1632 + row * ROWP + cP]     = sum2(a1[j]) + s_gb[800 + cP];
                    s_g[3264 + row * ROWP + cP]     = sum2(a2[j]) + s_gb[1000 + cP];
                }
            } else {
#pragma unroll
                for (int j = 0; j < 4; j++) {
                    xz[j] = sum2(a0[j]) + s_gb[cP];
                    xr[j] = sum2(a1[j]) + s_gb[200 + cP];
                    xh[j] = sum2(a2[j]) + s_gb[400 + cP];
                }
            }
        }
        __syncthreads();

        // ====== P3: gates, deter_n (x-side threads own it) ==================
        if (tid < 400) {
#pragma unroll
            for (int j = 0; j < 4; j++) {
                int row = rhP * 4 + j;
                int idx = row * ROWP + cP;
                float z  = sigmoid1(xz[j] + s_g[idx]);
                float rg = sigmoid1(xr[j] + s_g[1632 + idx]);
                float a  = xh[j] + rg * s_g[3264 + idx];
                float e2 = __expf(2.f * a);
                float th = 1.f - 2.f * rcpa(e2 + 1.f);
                float dn = z * pd[idx] + (1.f - z) * th;
                pn[idx] = dn;
                float* orow = out + ((size_t)(b0 + row) * TLEN + t) * 580;
                orow[90 + cP]  = dn;
                orow[380 + cP] = dn;
            }
        }
        __syncthreads();

        // ====== P4: x2 / xo, 1 col x 4 rows, twinned lanes ==================
        {
            const float* db = pn + rhP4 * 4 * ROWP;
            ull acc[4];
#pragma unroll
            for (int j = 0; j < 4; j++) acc[j] = 0ull;
            ulonglong2 w = ldg2(wpP4);
            for (int kq = 0; kq < 50; kq++) {
                const int kn = (kq < 49) ? kq + 1 : 49;
                ulonglong2 n = ldg2(wpP4 + kn * 200);
#pragma unroll
                for (int j = 0; j < 4; j++) {
                    ulonglong2 v = lds2(db + j * ROWP + 4 * kq);
                    acc[j] = fma2(v.x, w.x, acc[j]);
                    acc[j] = fma2(v.y, w.y, acc[j]);
                }
                w = n;
            }
            if (matP4 == 0) {
                float bb = s_b2[cP4];
#pragma unroll
                for (int j = 0; j < 4; j++) {
                    int row = rhP4 * 4 + j;
                    s_x[row * ROWP + cP4] = elu1(sum2(acc[j]) + bb);
                }
            } else {
#pragma unroll
                for (int j = 0; j < 4; j++) {
                    int row = rhP4 * 4 + j;
                    s_xo[row * ROWP + cP4] = elu1(sum2(acc[j]) + s_eo[row * ROWP + cP4]);
                }
            }
        }
        __syncthreads();

        // ====== P5: heads + samples fused (480 thr) + action prefetch =======
        if (tid < 480) {
            float nz = __ldg(nptr + (size_t)t * (BSZ * SDIM));

            const float* srcr = (pP5 ? s_x : s_xo) + rP5 * ROWP;
            ull am = 0ull, as = 0ull;
            ulonglong2 m0 = ldg2(wmP5);
            ulonglong2 s0 = ldg2(wsP5);
            for (int kq = 0; kq < 50; kq++) {
                int kn = (kq < 49) ? kq + 1 : 49;
                ulonglong2 mn = ldg2(wmP5 + kn * 30);
                ulonglong2 sn = ldg2(wsP5 + kn * 30);
                ulonglong2 v = lds2(srcr + 4 * kq);
                am = fma2(v.x, m0.x, am);
                am = fma2(v.y, m0.y, am);
                as = fma2(v.x, s0.x, as);
                as = fma2(v.y, s0.y, as);
                m0 = mn; s0 = sn;
            }
            float mean = sum2(am) + s_hb[2 * pP5 * 30 + sP5];
            float sdev = softplus1(sum2(as) + s_hb[(2 * pP5 + 1) * 30 + sP5]);
            if (pP5) sdev += 0.1f;
            float stoch = mean + sdev * nz;

            float* op = optr + (size_t)t * 580;
            op[0]  = mean;
            op[30] = sdev;
            op[60] = stoch;
            if (pP5 == 0) s_in[rP5 * INP + sP5] = stoch;  // posterior carry
        } else if (tid >= 752 && t + 1 < TLEN) {
            int idx = tid - 752;
            int r = idx / 6, j = idx % 6;
            s_in[r * INP + 30 + j] =
                action[(size_t)(b0 + r) * (TLEN * ADIM) + (t + 1) * ADIM + j];
        }

        { float* tmp = pd; pd = pn; pn = tmp; }
        __syncthreads();
    }
}

// ---------------------------------------------------------------------------
// Launch
// ---------------------------------------------------------------------------
extern "C" void kernel_launch(void* const* d_in, const int* in_sizes, int n_in,
                              void* d_out, int out_size) {
    const float* embed       = (const float*)d_in[0];
    const float* action      = (const float*)d_in[1];
    const float* noise_prior = (const float*)d_in[2];
    const float* noise_post  = (const float*)d_in[3];
    const float* w_img1      = (const float*)d_in[4];
    const float* b_img1      = (const float*)d_in[5];
    const float* gru_w       = (const float*)d_in[6];
    const float* gru_u       = (const float*)d_in[7];
    const float* gru_b       = (const float*)d_in[8];
    const float* gru_rb      = (const float*)d_in[9];
    const float* w_img2      = (const float*)d_in[10];
    const float* b_img2      = (const float*)d_in[11];
    const float* w_imean     = (const float*)d_in[12];
    const float* b_imean     = (const float*)d_in[13];
    const float* w_istd      = (const float*)d_in[14];
    const float* b_istd      = (const float*)d_in[15];
    const float* w_obs1      = (const float*)d_in[16];
    const float* b_obs1      = (const float*)d_in[17];
    const float* w_omean     = (const float*)d_in[18];
    const float* b_omean     = (const float*)d_in[19];
    const float* w_ostd      = (const float*)d_in[20];
    const float* b_ostd      = (const float*)d_in[21];
    float* out = (float*)d_out;

    repack_kernel<<<(556000 + 255) / 256, 256>>>(w_img1, gru_w, gru_u, w_img2,
                                                 w_obs1, w_omean, w_ostd,
                                                 w_imean, w_istd);
    eo_gemm_kernel<<<BSZ * TLEN / 64, 640>>>(embed, b_obs1);
    rssm_recur_kernel<<<BSZ / 8, 800>>>(action, noise_prior, noise_post,
                                        b_img1, gru_b, gru_rb, b_img2,
                                        b_imean, b_istd, b_omean, b_ostd, out);
}

// round 16
// speedup vs baseline: 1.0781x; 1.0089x over previous
#include <cuda_runtime.h>

#define BSZ   1024
#define TLEN  64
#define SDIM  30
#define DDIM  200
#define HDIM  200
#define EDIM  1024
#define ADIM  6

// rows per recur CTA (7 valid + 1 ghost pad row in smem)
#define RPC   7

// padded row strides (floats) to keep lane-pair LDS conflict-free
#define ROWP  204     // activation rows (200 data + 4 pad); 4*204 % 32 == 16
#define INP   44      // s_in rows (36 data + pad); 4*44 % 32 == 16

typedef unsigned long long ull;

// ---------------------------------------------------------------------------
// Device scratch
// ---------------------------------------------------------------------------
__device__ float g_eo[(size_t)BSZ * TLEN * HDIM];   // embed @ w_obs1[200:] + b_obs1

// k-quad packed weights (float4 = 4 consecutive k values for one output col)
__device__ float4 g_gru4[6 * 50 * 200];  // [st][kq][c]; st: Wz,Wr,Wh,Uz,Ur,Uh
__device__ float4 g_p4[2 * 50 * 200];    // [mat][kq][c]; mat: img2, obs1d
__device__ float4 g_i14[9 * 200];        // img1 [kq][c], K=36
__device__ float4 g_h4[4 * 50 * 30];     // heads [h][kq][s]
// eo weights, k-pair interleaved: float idx ((kp*200 + c)*2 + p), kp 0..511
__device__ ull    g_wep[102400];

// ---------------------------------------------------------------------------
// Helpers
// ---------------------------------------------------------------------------
__device__ __forceinline__ ull fma2(ull a, ull b, ull c) {
    ull d;
    asm("fma.rn.f32x2 %0, %1, %2, %3;" : "=l"(d) : "l"(a), "l"(b), "l"(c));
    return d;
}
__device__ __forceinline__ float sum2(ull a) {
    float2 f;
    asm("mov.b64 {%0, %1}, %2;" : "=f"(f.x), "=f"(f.y) : "l"(a));
    return f.x + f.y;
}
__device__ __forceinline__ ulonglong2 ldg2(const float4* p) {
    return __ldg(reinterpret_cast<const ulonglong2*>(p));
}
__device__ __forceinline__ ulonglong2 lds2(const float* p) {
    return *reinterpret_cast<const ulonglong2*>(p);
}
__device__ __forceinline__ float rcpa(float x) {
    float r;
    asm("rcp.approx.f32 %0, %1;" : "=f"(r) : "f"(x));
    return r;
}
__device__ __forceinline__ float elu1(float v) {
    return v > 0.f ? v : (__expf(v) - 1.f);
}
__device__ __forceinline__ float softplus1(float x) {
    return fmaxf(x, 0.f) + __logf(1.f + __expf(-fabsf(x)));
}
__device__ __forceinline__ float sigmoid1(float x) {
    return rcpa(1.f + __expf(-x));
}
__device__ __forceinline__ void cp16(void* s, const void* g) {
    unsigned ss = (unsigned)__cvta_generic_to_shared(s);
    asm volatile("cp.async.ca.shared.global [%0], [%1], 16;" :: "r"(ss), "l"(g) : "memory");
}
#define CP_COMMIT() asm volatile("cp.async.commit_group;" ::: "memory")
#define CP_WAIT1()  asm volatile("cp.async.wait_group 1;" ::: "memory")
#define CP_WAIT0()  asm volatile("cp.async.wait_group 0;" ::: "memory")

// ---------------------------------------------------------------------------
// Repack kernel: k-quad layouts + g_wep
// ---------------------------------------------------------------------------
__global__ void repack_kernel(const float* __restrict__ w_img1,
                              const float* __restrict__ gru_w,
                              const float* __restrict__ gru_u,
                              const float* __restrict__ w_img2,
                              const float* __restrict__ w_obs1,
                              const float* __restrict__ w_omean,
                              const float* __restrict__ w_ostd,
                              const float* __restrict__ w_imean,
                              const float* __restrict__ w_istd) {
    int i = blockIdx.x * 256 + threadIdx.x;
    if (i < 240000) {                       // GRU 6 streams
        int f = i & 3, q = i >> 2;
        int st = q / 10000, rem = q % 10000, kq = rem / 200, cc = rem % 200;
        int k = 4 * kq + f;
        float v = (st < 3) ? gru_w[k * 600 + st * 200 + cc]
                           : gru_u[k * 600 + (st - 3) * 200 + cc];
        ((float*)g_gru4)[i] = v;
    } else if (i < 320000) {                // img2 / obs1d
        int j = i - 240000;
        int f = j & 3, q = j >> 2;
        int mat = q / 10000, rem = q % 10000, kq = rem / 200, cc = rem % 200;
        int k = 4 * kq + f;
        ((float*)g_p4)[j] = (mat == 0) ? w_img2[k * 200 + cc] : w_obs1[k * 200 + cc];
    } else if (i < 327200) {                // img1
        int j = i - 320000;
        int f = j & 3, q = j >> 2;
        int kq = q / 200, cc = q % 200;
        int k = 4 * kq + f;
        ((float*)g_i14)[j] = w_img1[k * 200 + cc];
    } else if (i < 351200) {                // heads
        int j = i - 327200;
        int f = j & 3, q = j >> 2;
        int h = q / 1500, rem = q % 1500, kq = rem / 30, s = rem % 30;
        int k = 4 * kq + f;
        const float* src = (h == 0) ? w_omean : (h == 1) ? w_ostd
                         : (h == 2) ? w_imean : w_istd;
        ((float*)g_h4)[j] = src[k * 30 + s];
    } else if (i < 556000) {                // eo weights (embed rows of w_obs1)
        int j = i - 351200;                 // (kp*200+c)*2 + p
        int p = j & 1, q = j >> 1;
        int c = q % 200, kp = q / 200;
        ((float*)g_wep)[j] = w_obs1[(size_t)(200 + 2 * kp + p) * 200 + c];
    }
}

// ---------------------------------------------------------------------------
// Kernel 1: eo GEMM, cp.async 3-stage pipeline, 320 threads (proven).
// ---------------------------------------------------------------------------
__global__ __launch_bounds__(320, 1)
void eo_gemm_kernel(const float* __restrict__ embed,
                    const float* __restrict__ b_obs1) {
    __shared__ __align__(16) float sbuf[3 * 8448];

    const int tid = threadIdx.x;
    const int tx = tid % 40;
    const int ty = tid / 40;
    const int m0 = blockIdx.x * 64;

    ull acc[8][5];
#pragma unroll
    for (int r = 0; r < 8; r++)
#pragma unroll
        for (int j = 0; j < 5; j++) acc[r][j] = 0ull;

    auto issue_chunk = [&](int cc) {
        const int k0 = cc * 32;
        float* dst = sbuf + (cc % 3) * 8448;
        for (int i = tid; i < 512; i += 320) {
            int r = i >> 3, q = i & 7;
            cp16(dst + r * 32 + q * 4,
                 embed + (size_t)(m0 + r) * 1024 + k0 + q * 4);
        }
        const float* wsrc = (const float*)g_wep + (size_t)(k0 >> 1) * 400;
        float* wdst = dst + 2048;
        for (int i = tid; i < 1600; i += 320) {
            cp16(wdst + i * 4, wsrc + i * 4);
        }
        CP_COMMIT();
    };

    issue_chunk(0);
    issue_chunk(1);

    for (int c = 0; c < 32; c++) {
        if (c < 31) { CP_WAIT1(); } else { CP_WAIT0(); }
        __syncthreads();
        if (c + 2 < 32) issue_chunk(c + 2);

        const float* bs = sbuf + (c % 3) * 8448;
        const ull* as_u = (const ull*)bs;
        const ull* ws_u = (const ull*)(bs + 2048);
#pragma unroll
        for (int kp = 0; kp < 16; kp++) {
            ull wv[5];
#pragma unroll
            for (int j = 0; j < 5; j++) wv[j] = ws_u[kp * 200 + tx * 5 + j];
#pragma unroll
            for (int r = 0; r < 8; r++) {
                ull av = as_u[(ty * 8 + r) * 16 + kp];
#pragma unroll
                for (int j = 0; j < 5; j++) acc[r][j] = fma2(av, wv[j], acc[r][j]);
            }
        }
        __syncthreads();
    }

#pragma unroll
    for (int r = 0; r < 8; r++) {
        int m = m0 + ty * 8 + r;
#pragma unroll
        for (int j = 0; j < 5; j++) {
            int cc = tx * 5 + j;
            g_eo[(size_t)m * 200 + cc] = sum2(acc[r][j]) + b_obs1[cc];
        }
    }
}

// ---------------------------------------------------------------------------
// Kernel 2: persistent recurrent kernel, 7 rows/CTA + 1 ghost row.
// 147 CTAs (full 148-SM coverage), 800 threads, 5 barriers/step,
// lane-pair twinning. Ghost row computes on zeros; all global loads/stores
// guarded by row < NR, so valid outputs are bit-identical to the 8-row map.
// ---------------------------------------------------------------------------
__global__ __launch_bounds__(800, 1)
void rssm_recur_kernel(const float* __restrict__ action,
                       const float* __restrict__ noise_prior,
                       const float* __restrict__ noise_post,
                       const float* __restrict__ b_img1,
                       const float* __restrict__ gru_b,
                       const float* __restrict__ gru_rb,
                       const float* __restrict__ b_img2,
                       const float* __restrict__ b_imean,
                       const float* __restrict__ b_istd,
                       const float* __restrict__ b_omean,
                       const float* __restrict__ b_ostd,
                       float* __restrict__ out) {
    __shared__ __align__(16) float sm[15128];
    float* s_in = sm;             // [8][INP]                              352
    float* det0 = sm + 352;       // [8][ROWP]                            1632
    float* det1 = sm + 1984;      // [8][ROWP]
    float* s_x  = sm + 3616;      // [8][ROWP]  img1 out, later x2
    float* s_xo = sm + 5248;      // [8][ROWP]
    float* s_eo = sm + 6880;      // [8][ROWP]
    float* s_g  = sm + 8512;      // [3][8][ROWP] d-side GRU partials     4896
    float* s_b1 = sm + 13408;     // [200]
    float* s_b2 = sm + 13608;     // [200]
    float* s_gb = sm + 13808;     // [6][200]
    float* s_hb = sm + 15008;     // [4][30]

    const int tid = threadIdx.x;
    const int b0 = blockIdx.x * RPC;
    const int NR = min(RPC, BSZ - b0);    // valid rows in this CTA

    // ---- P2 mapping: (side, c, rh) with rh in the lane LSB ----
    const int sgP = tid / 400;            // 0: x-side, 1: d-side
    const int cP  = (tid % 400) >> 1;     // 0..199
    const int rhP = tid & 1;              // row half
    const float4* wpP2 = g_gru4 + sgP * 30000 + cP;

    // ---- P4 mapping ----
    const int matP4 = tid / 400;
    const int cP4   = (tid % 400) >> 1;
    const int rhP4  = tid & 1;
    const float4* wpP4 = g_p4 + matP4 * 10000 + cP4;

    // ---- P5 mapping (tid < 480): pair p (0=post,1=prior), row r, col s ----
    const int pP5 = tid / 240;
    const int remP5 = tid % 240;
    const int rP5 = remP5 / 30;
    const int sP5 = remP5 % 30;
    const bool vP5 = (tid < 480) && (rP5 < NR);
    const float* nptr = (pP5 ? noise_prior : noise_post)
                        + (size_t)(b0 + rP5) * SDIM + sP5;
    float* optr = out + (size_t)(b0 + rP5) * TLEN * 580 + (pP5 ? 290 : 0) + sP5;
    const float4* wmP5 = g_h4 + (2 * pP5) * 1500 + sP5;
    const float4* wsP5 = g_h4 + (2 * pP5 + 1) * 1500 + sP5;

    // ---- init: biases to smem, carry zeros, action[0] ----
    if (tid < 200) {
        s_b1[tid] = b_img1[tid];
        s_b2[tid] = b_img2[tid];
    }
    for (int i = tid; i < 1200; i += 800) {
        int st = i / 200, cc = i % 200;
        s_gb[i] = (st < 3) ? gru_b[st * 200 + cc] : gru_rb[(st - 3) * 200 + cc];
    }
    if (tid < 120) {
        int h = tid / 30, s = tid % 30;
        s_hb[tid] = (h == 0) ? b_omean[s] : (h == 1) ? b_ostd[s]
                  : (h == 2) ? b_imean[s] : b_istd[s];
    }
    for (int i = tid; i < 8 * INP; i += 800) s_in[i] = 0.f;
    for (int i = tid; i < 8 * ROWP; i += 800) {
        det0[i] = 0.f;
        s_eo[i] = 0.f;      // ghost rows stay zero forever
    }
    if (tid < 48) {
        int r = tid / 6, j = tid % 6;
        if (r < NR)
            s_in[r * INP + 30 + j] = action[(size_t)(b0 + r) * (TLEN * ADIM) + j];
    }
    float* pd = det0;
    float* pn = det1;
    __syncthreads();

    for (int t = 0; t < TLEN; ++t) {
        // ====== P1: x = elu([stoch,action]@W1 + b)  |  eo loads =============
        if (tid < 400) {
            const int c = tid >> 1, rh = tid & 1;
            ull acc[4];
#pragma unroll
            for (int j = 0; j < 4; j++) acc[j] = 0ull;
#pragma unroll
            for (int kq = 0; kq < 9; kq++) {
                ulonglong2 w = ldg2(g_i14 + kq * 200 + c);
#pragma unroll
                for (int j = 0; j < 4; j++) {
                    ulonglong2 v = lds2(s_in + (rh * 4 + j) * INP + 4 * kq);
                    acc[j] = fma2(v.x, w.x, acc[j]);
                    acc[j] = fma2(v.y, w.y, acc[j]);
                }
            }
            float bb = s_b1[c];
#pragma unroll
            for (int j = 0; j < 4; j++)
                s_x[(rh * 4 + j) * ROWP + c] = elu1(sum2(acc[j]) + bb);
        } else if (tid >= 600) {
            int t2 = tid - 600;
#pragma unroll
            for (int i = 0; i < RPC; i++) {
                if (i < NR)
                    s_eo[i * ROWP + t2] =
                        __ldg(&g_eo[((size_t)(b0 + i) * TLEN + t) * 200 + t2]);
            }
        }
        __syncthreads();

        // ====== P2: 3 streams x 1 col x 4 rows, twinned lanes ===============
        float xz[4], xr[4], xh[4];   // x-side results (sgP==0 only)
        {
            const float* src = sgP ? pd : s_x;
            const float* srb = src + rhP * 4 * ROWP;
            ull a0[4], a1[4], a2[4];
#pragma unroll
            for (int j = 0; j < 4; j++) { a0[j] = 0; a1[j] = 0; a2[j] = 0; }
            ulonglong2 w0 = ldg2(wpP2);
            ulonglong2 w1 = ldg2(wpP2 + 10000);
            ulonglong2 w2 = ldg2(wpP2 + 20000);
            for (int kq = 0; kq < 50; kq++) {
                const int kn = (kq < 49) ? kq + 1 : 49;
                ulonglong2 n0 = ldg2(wpP2 + kn * 200);
                ulonglong2 n1 = ldg2(wpP2 + 10000 + kn * 200);
                ulonglong2 n2 = ldg2(wpP2 + 20000 + kn * 200);
#pragma unroll
                for (int j = 0; j < 4; j++) {
                    ulonglong2 v = lds2(srb + j * ROWP + 4 * kq);
                    a0[j] = fma2(v.x, w0.x, a0[j]);
                    a0[j] = fma2(v.y, w0.y, a0[j]);
                    a1[j] = fma2(v.x, w1.x, a1[j]);
                    a1[j] = fma2(v.y, w1.y, a1[j]);
                    a2[j] = fma2(v.x, w2.x, a2[j]);
                    a2[j] = fma2(v.y, w2.y, a2[j]);
                }
                w0 = n0; w1 = n1; w2 = n2;
            }
            if (sgP) {
#pragma unroll
                for (int j = 0; j < 4; j++) {
                    int row = rhP * 4 + j;
                    s_g[row * ROWP + cP]            = sum2(a0[j]) + s_gb[600 + cP];
                    s_g[1632 + row * ROWP + cP]     = sum2(a1[j]) + s_gb[800 + cP];
                    s_g[3264 + row * ROWP + cP]     = sum2(a2[j]) + s_gb[1000 + cP];
                }
            } else {
#pragma unroll
                for (int j = 0; j < 4; j++) {
                    xz[j] = sum2(a0[j]) + s_gb[cP];
                    xr[j] = sum2(a1[j]) + s_gb[200 + cP];
                    xh[j] = sum2(a2[j]) + s_gb[400 + cP];
                }
            }
        }
        __syncthreads();

        // ====== P3: gates, deter_n (x-side threads own it) ==================
        if (tid < 400) {
#pragma unroll
            for (int j = 0; j < 4; j++) {
                int row = rhP * 4 + j;
                int idx = row * ROWP + cP;
                float z  = sigmoid1(xz[j] + s_g[idx]);
                float rg = sigmoid1(xr[j] + s_g[1632 + idx]);
                float a  = xh[j] + rg * s_g[3264 + idx];
                float e2 = __expf(2.f * a);
                float th = 1.f - 2.f * rcpa(e2 + 1.f);
                float dn = z * pd[idx] + (1.f - z) * th;
                pn[idx] = dn;
                if (row < NR) {
                    float* orow = out + ((size_t)(b0 + row) * TLEN + t) * 580;
                    orow[90 + cP]  = dn;
                    orow[380 + cP] = dn;
                }
            }
        }
        __syncthreads();

        // ====== P4: x2 / xo, 1 col x 4 rows, twinned lanes ==================
        {
            const float* db = pn + rhP4 * 4 * ROWP;
            ull acc[4];
#pragma unroll
            for (int j = 0; j < 4; j++) acc[j] = 0ull;
            ulonglong2 w = ldg2(wpP4);
            for (int kq = 0; kq < 50; kq++) {
                const int kn = (kq < 49) ? kq + 1 : 49;
                ulonglong2 n = ldg2(wpP4 + kn * 200);
#pragma unroll
                for (int j = 0; j < 4; j++) {
                    ulonglong2 v = lds2(db + j * ROWP + 4 * kq);
                    acc[j] = fma2(v.x, w.x, acc[j]);
                    acc[j] = fma2(v.y, w.y, acc[j]);
                }
                w = n;
            }
            if (matP4 == 0) {
                float bb = s_b2[cP4];
#pragma unroll
                for (int j = 0; j < 4; j++) {
                    int row = rhP4 * 4 + j;
                    s_x[row * ROWP + cP4] = elu1(sum2(acc[j]) + bb);
                }
            } else {
#pragma unroll
                for (int j = 0; j < 4; j++) {
                    int row = rhP4 * 4 + j;
                    s_xo[row * ROWP + cP4] = elu1(sum2(acc[j]) + s_eo[row * ROWP + cP4]);
                }
            }
        }
        __syncthreads();

        // ====== P5: heads + samples fused (480 thr) + action prefetch =======
        if (tid < 480) {
            float nz = vP5 ? __ldg(nptr + (size_t)t * (BSZ * SDIM)) : 0.f;

            const float* srcr = (pP5 ? s_x : s_xo) + rP5 * ROWP;
            ull am = 0ull, as = 0ull;
            ulonglong2 m0 = ldg2(wmP5);
            ulonglong2 s0 = ldg2(wsP5);
            for (int kq = 0; kq < 50; kq++) {
                int kn = (kq < 49) ? kq + 1 : 49;
                ulonglong2 mn = ldg2(wmP5 + kn * 30);
                ulonglong2 sn = ldg2(wsP5 + kn * 30);
                ulonglong2 v = lds2(srcr + 4 * kq);
                am = fma2(v.x, m0.x, am);
                am = fma2(v.y, m0.y, am);
                as = fma2(v.x, s0.x, as);
                as = fma2(v.y, s0.y, as);
                m0 = mn; s0 = sn;
            }
            float mean = sum2(am) + s_hb[2 * pP5 * 30 + sP5];
            float sdev = softplus1(sum2(as) + s_hb[(2 * pP5 + 1) * 30 + sP5]);
            if (pP5) sdev += 0.1f;
            float stoch = mean + sdev * nz;

            if (vP5) {
                float* op = optr + (size_t)t * 580;
                op[0]  = mean;
                op[30] = sdev;
                op[60] = stoch;
                if (pP5 == 0) s_in[rP5 * INP + sP5] = stoch;  // posterior carry
            }
        } else if (tid >= 752 && t + 1 < TLEN) {
            int idx = tid - 752;
            int r = idx / 6, j = idx % 6;
            if (r < NR)
                s_in[r * INP + 30 + j] =
                    action[(size_t)(b0 + r) * (TLEN * ADIM) + (t + 1) * ADIM + j];
        }

        { float* tmp = pd; pd = pn; pn = tmp; }
        __syncthreads();
    }
}

// ---------------------------------------------------------------------------
// Launch
// ---------------------------------------------------------------------------
extern "C" void kernel_launch(void* const* d_in, const int* in_sizes, int n_in,
                              void* d_out, int out_size) {
    const float* embed       = (const float*)d_in[0];
    const float* action      = (const float*)d_in[1];
    const float* noise_prior = (const float*)d_in[2];
    const float* noise_post  = (const float*)d_in[3];
    const float* w_img1      = (const float*)d_in[4];
    const float* b_img1      = (const float*)d_in[5];
    const float* gru_w       = (const float*)d_in[6];
    const float* gru_u       = (const float*)d_in[7];
    const float* gru_b       = (const float*)d_in[8];
    const float* gru_rb      = (const float*)d_in[9];
    const float* w_img2      = (const float*)d_in[10];
    const float* b_img2      = (const float*)d_in[11];
    const float* w_imean     = (const float*)d_in[12];
    const float* b_imean     = (const float*)d_in[13];
    const float* w_istd      = (const float*)d_in[14];
    const float* b_istd      = (const float*)d_in[15];
    const float* w_obs1      = (const float*)d_in[16];
    const float* b_obs1      = (const float*)d_in[17];
    const float* w_omean     = (const float*)d_in[18];
    const float* b_omean     = (const float*)d_in[19];
    const float* w_ostd      = (const float*)d_in[20];
    const float* b_ostd      = (const float*)d_in[21];
    float* out = (float*)d_out;

    repack_kernel<<<(556000 + 255) / 256, 256>>>(w_img1, gru_w, gru_u, w_img2,
                                                 w_obs1, w_omean, w_ostd,
                                                 w_imean, w_istd);
    eo_gemm_kernel<<<BSZ * TLEN / 64, 320>>>(embed, b_obs1);
    rssm_recur_kernel<<<(BSZ + RPC - 1) / RPC, 800>>>(action, noise_prior, noise_post,
                                                      b_img1, gru_b, gru_rb, b_img2,
                                                      b_imean, b_istd, b_omean, b_ostd, out);
}

// round 17
// speedup vs baseline: 1.0793x; 1.0011x over previous
#include <cuda_runtime.h>

#define BSZ   1024
#define TLEN  64
#define SDIM  30
#define DDIM  200
#define HDIM  200
#define EDIM  1024
#define ADIM  6

// rows per recur CTA (7 valid + 1 ghost pad row in smem)
#define RPC   7

// padded row strides (floats) to keep lane-pair LDS conflict-free
#define ROWP  204     // activation rows (200 data + 4 pad); 4*204 % 32 == 16
#define INP   44      // s_in rows (36 data + pad); 4*44 % 32 == 16

// eo buffer geometry: as 64x32 floats padded +4 floats per 8-row group (2080)
// + ws 6400 floats = 8480 floats per stage
#define EOBUF 8480

typedef unsigned long long ull;

// ---------------------------------------------------------------------------
// Device scratch
// ---------------------------------------------------------------------------
__device__ float g_eo[(size_t)BSZ * TLEN * HDIM];   // embed @ w_obs1[200:] + b_obs1

// k-quad packed weights (float4 = 4 consecutive k values for one output col)
__device__ float4 g_gru4[6 * 50 * 200];  // [st][kq][c]; st: Wz,Wr,Wh,Uz,Ur,Uh
__device__ float4 g_p4[2 * 50 * 200];    // [mat][kq][c]; mat: img2, obs1d
__device__ float4 g_i14[9 * 200];        // img1 [kq][c], K=36
__device__ float4 g_h4[4 * 50 * 30];     // heads [h][kq][s]
// eo weights, k-pair interleaved: float idx ((kp*200 + c)*2 + p), kp 0..511
__device__ ull    g_wep[102400];

// ---------------------------------------------------------------------------
// Helpers
// ---------------------------------------------------------------------------
__device__ __forceinline__ ull fma2(ull a, ull b, ull c) {
    ull d;
    asm("fma.rn.f32x2 %0, %1, %2, %3;" : "=l"(d) : "l"(a), "l"(b), "l"(c));
    return d;
}
__device__ __forceinline__ float sum2(ull a) {
    float2 f;
    asm("mov.b64 {%0, %1}, %2;" : "=f"(f.x), "=f"(f.y) : "l"(a));
    return f.x + f.y;
}
__device__ __forceinline__ ulonglong2 ldg2(const float4* p) {
    return __ldg(reinterpret_cast<const ulonglong2*>(p));
}
__device__ __forceinline__ ulonglong2 lds2(const float* p) {
    return *reinterpret_cast<const ulonglong2*>(p);
}
__device__ __forceinline__ float rcpa(float x) {
    float r;
    asm("rcp.approx.f32 %0, %1;" : "=f"(r) : "f"(x));
    return r;
}
__device__ __forceinline__ float elu1(float v) {
    return v > 0.f ? v : (__expf(v) - 1.f);
}
__device__ __forceinline__ float softplus1(float x) {
    return fmaxf(x, 0.f) + __logf(1.f + __expf(-fabsf(x)));
}
__device__ __forceinline__ float sigmoid1(float x) {
    return rcpa(1.f + __expf(-x));
}
__device__ __forceinline__ void cp16(void* s, const void* g) {
    unsigned ss = (unsigned)__cvta_generic_to_shared(s);
    asm volatile("cp.async.ca.shared.global [%0], [%1], 16;" :: "r"(ss), "l"(g) : "memory");
}
#define CP_COMMIT() asm volatile("cp.async.commit_group;" ::: "memory")
#define CP_WAIT1()  asm volatile("cp.async.wait_group 1;" ::: "memory")
#define CP_WAIT0()  asm volatile("cp.async.wait_group 0;" ::: "memory")

// ---------------------------------------------------------------------------
// Repack kernel: k-quad layouts + g_wep
// ---------------------------------------------------------------------------
__global__ void repack_kernel(const float* __restrict__ w_img1,
                              const float* __restrict__ gru_w,
                              const float* __restrict__ gru_u,
                              const float* __restrict__ w_img2,
                              const float* __restrict__ w_obs1,
                              const float* __restrict__ w_omean,
                              const float* __restrict__ w_ostd,
                              const float* __restrict__ w_imean,
                              const float* __restrict__ w_istd) {
    int i = blockIdx.x * 256 + threadIdx.x;
    if (i < 240000) {                       // GRU 6 streams
        int f = i & 3, q = i >> 2;
        int st = q / 10000, rem = q % 10000, kq = rem / 200, cc = rem % 200;
        int k = 4 * kq + f;
        float v = (st < 3) ? gru_w[k * 600 + st * 200 + cc]
                           : gru_u[k * 600 + (st - 3) * 200 + cc];
        ((float*)g_gru4)[i] = v;
    } else if (i < 320000) {                // img2 / obs1d
        int j = i - 240000;
        int f = j & 3, q = j >> 2;
        int mat = q / 10000, rem = q % 10000, kq = rem / 200, cc = rem % 200;
        int k = 4 * kq + f;
        ((float*)g_p4)[j] = (mat == 0) ? w_img2[k * 200 + cc] : w_obs1[k * 200 + cc];
    } else if (i < 327200) {                // img1
        int j = i - 320000;
        int f = j & 3, q = j >> 2;
        int kq = q / 200, cc = q % 200;
        int k = 4 * kq + f;
        ((float*)g_i14)[j] = w_img1[k * 200 + cc];
    } else if (i < 351200) {                // heads
        int j = i - 327200;
        int f = j & 3, q = j >> 2;
        int h = q / 1500, rem = q % 1500, kq = rem / 30, s = rem % 30;
        int k = 4 * kq + f;
        const float* src = (h == 0) ? w_omean : (h == 1) ? w_ostd
                         : (h == 2) ? w_imean : w_istd;
        ((float*)g_h4)[j] = src[k * 30 + s];
    } else if (i < 556000) {                // eo weights (embed rows of w_obs1)
        int j = i - 351200;                 // (kp*200+c)*2 + p
        int p = j & 1, q = j >> 1;
        int c = q % 200, kp = q / 200;
        ((float*)g_wep)[j] = w_obs1[(size_t)(200 + 2 * kp + p) * 200 + c];
    }
}

// ---------------------------------------------------------------------------
// Kernel 1: eo GEMM, cp.async 3-stage pipeline, 320 threads.
// tx-major lane map: tx = tid>>3 (cols), ty = tid&7 (rows) -> weight LDS
// 8-way broadcast, activation LDS 4-way broadcast within each warp.
// as-buffer padded +2 ull per 8-row group: ty word-stride 260 % 32 = 4 ->
// the 8 ty addresses hit 8 distinct banks (no conflict).
// ---------------------------------------------------------------------------
__global__ __launch_bounds__(320, 1)
void eo_gemm_kernel(const float* __restrict__ embed,
                    const float* __restrict__ b_obs1) {
    __shared__ __align__(16) float sbuf[3 * EOBUF];

    const int tid = threadIdx.x;
    const int tx = tid >> 3;      // 0..39, 5 cols each
    const int ty = tid & 7;       // 0..7, 8 rows each
    const int m0 = blockIdx.x * 64;

    ull acc[8][5];
#pragma unroll
    for (int r = 0; r < 8; r++)
#pragma unroll
        for (int j = 0; j < 5; j++) acc[r][j] = 0ull;

    auto issue_chunk = [&](int cc) {
        const int k0 = cc * 32;
        float* dst = sbuf + (cc % 3) * EOBUF;
        for (int i = tid; i < 512; i += 320) {
            int r = i >> 3, q = i & 7;
            cp16(dst + r * 32 + (r >> 3) * 4 + q * 4,
                 embed + (size_t)(m0 + r) * 1024 + k0 + q * 4);
        }
        const float* wsrc = (const float*)g_wep + (size_t)(k0 >> 1) * 400;
        float* wdst = dst + 2080;
        for (int i = tid; i < 1600; i += 320) {
            cp16(wdst + i * 4, wsrc + i * 4);
        }
        CP_COMMIT();
    };

    issue_chunk(0);
    issue_chunk(1);

    for (int c = 0; c < 32; c++) {
        if (c < 31) { CP_WAIT1(); } else { CP_WAIT0(); }
        __syncthreads();
        if (c + 2 < 32) issue_chunk(c + 2);

        const float* bs = sbuf + (c % 3) * EOBUF;
        const ull* as_u = (const ull*)bs;                 // [ty*130 + r*16 + kp]
        const ull* ws_u = (const ull*)(bs + 2080);
#pragma unroll
        for (int kp = 0; kp < 16; kp++) {
            ull wv[5];
#pragma unroll
            for (int j = 0; j < 5; j++) wv[j] = ws_u[kp * 200 + tx * 5 + j];
#pragma unroll
            for (int r = 0; r < 8; r++) {
                ull av = as_u[ty * 130 + r * 16 + kp];
#pragma unroll
                for (int j = 0; j < 5; j++) acc[r][j] = fma2(av, wv[j], acc[r][j]);
            }
        }
        __syncthreads();
    }

#pragma unroll
    for (int r = 0; r < 8; r++) {
        int m = m0 + ty * 8 + r;
#pragma unroll
        for (int j = 0; j < 5; j++) {
            int cc = tx * 5 + j;
            g_eo[(size_t)m * 200 + cc] = sum2(acc[r][j]) + b_obs1[cc];
        }
    }
}

// ---------------------------------------------------------------------------
// Kernel 2: persistent recurrent kernel (round-16 proven, verbatim).
// 147 CTAs x 7 rows (+1 ghost), 800 threads, 5 barriers/step, lane twinning.
// ---------------------------------------------------------------------------
__global__ __launch_bounds__(800, 1)
void rssm_recur_kernel(const float* __restrict__ action,
                       const float* __restrict__ noise_prior,
                       const float* __restrict__ noise_post,
                       const float* __restrict__ b_img1,
                       const float* __restrict__ gru_b,
                       const float* __restrict__ gru_rb,
                       const float* __restrict__ b_img2,
                       const float* __restrict__ b_imean,
                       const float* __restrict__ b_istd,
                       const float* __restrict__ b_omean,
                       const float* __restrict__ b_ostd,
                       float* __restrict__ out) {
    __shared__ __align__(16) float sm[15128];
    float* s_in = sm;             // [8][INP]                              352
    float* det0 = sm + 352;       // [8][ROWP]                            1632
    float* det1 = sm + 1984;      // [8][ROWP]
    float* s_x  = sm + 3616;      // [8][ROWP]  img1 out, later x2
    float* s_xo = sm + 5248;      // [8][ROWP]
    float* s_eo = sm + 6880;      // [8][ROWP]
    float* s_g  = sm + 8512;      // [3][8][ROWP] d-side GRU partials     4896
    float* s_b1 = sm + 13408;     // [200]
    float* s_b2 = sm + 13608;     // [200]
    float* s_gb = sm + 13808;     // [6][200]
    float* s_hb = sm + 15008;     // [4][30]

    const int tid = threadIdx.x;
    const int b0 = blockIdx.x * RPC;
    const int NR = min(RPC, BSZ - b0);    // valid rows in this CTA

    // ---- P2 mapping: (side, c, rh) with rh in the lane LSB ----
    const int sgP = tid / 400;            // 0: x-side, 1: d-side
    const int cP  = (tid % 400) >> 1;     // 0..199
    const int rhP = tid & 1;              // row half
    const float4* wpP2 = g_gru4 + sgP * 30000 + cP;

    // ---- P4 mapping ----
    const int matP4 = tid / 400;
    const int cP4   = (tid % 400) >> 1;
    const int rhP4  = tid & 1;
    const float4* wpP4 = g_p4 + matP4 * 10000 + cP4;

    // ---- P5 mapping (tid < 480): pair p (0=post,1=prior), row r, col s ----
    const int pP5 = tid / 240;
    const int remP5 = tid % 240;
    const int rP5 = remP5 / 30;
    const int sP5 = remP5 % 30;
    const bool vP5 = (tid < 480) && (rP5 < NR);
    const float* nptr = (pP5 ? noise_prior : noise_post)
                        + (size_t)(b0 + rP5) * SDIM + sP5;
    float* optr = out + (size_t)(b0 + rP5) * TLEN * 580 + (pP5 ? 290 : 0) + sP5;
    const float4* wmP5 = g_h4 + (2 * pP5) * 1500 + sP5;
    const float4* wsP5 = g_h4 + (2 * pP5 + 1) * 1500 + sP5;

    // ---- init: biases to smem, carry zeros, action[0] ----
    if (tid < 200) {
        s_b1[tid] = b_img1[tid];
        s_b2[tid] = b_img2[tid];
    }
    for (int i = tid; i < 1200; i += 800) {
        int st = i / 200, cc = i % 200;
        s_gb[i] = (st < 3) ? gru_b[st * 200 + cc] : gru_rb[(st - 3) * 200 + cc];
    }
    if (tid < 120) {
        int h = tid / 30, s = tid % 30;
        s_hb[tid] = (h == 0) ? b_omean[s] : (h == 1) ? b_ostd[s]
                  : (h == 2) ? b_imean[s] : b_istd[s];
    }
    for (int i = tid; i < 8 * INP; i += 800) s_in[i] = 0.f;
    for (int i = tid; i < 8 * ROWP; i += 800) {
        det0[i] = 0.f;
        s_eo[i] = 0.f;      // ghost rows stay zero forever
    }
    if (tid < 48) {
        int r = tid / 6, j = tid % 6;
        if (r < NR)
            s_in[r * INP + 30 + j] = action[(size_t)(b0 + r) * (TLEN * ADIM) + j];
    }
    float* pd = det0;
    float* pn = det1;
    __syncthreads();

    for (int t = 0; t < TLEN; ++t) {
        // ====== P1: x = elu([stoch,action]@W1 + b)  |  eo loads =============
        if (tid < 400) {
            const int c = tid >> 1, rh = tid & 1;
            ull acc[4];
#pragma unroll
            for (int j = 0; j < 4; j++) acc[j] = 0ull;
#pragma unroll
            for (int kq = 0; kq < 9; kq++) {
                ulonglong2 w = ldg2(g_i14 + kq * 200 + c);
#pragma unroll
                for (int j = 0; j < 4; j++) {
                    ulonglong2 v = lds2(s_in + (rh * 4 + j) * INP + 4 * kq);
                    acc[j] = fma2(v.x, w.x, acc[j]);
                    acc[j] = fma2(v.y, w.y, acc[j]);
                }
            }
            float bb = s_b1[c];
#pragma unroll
            for (int j = 0; j < 4; j++)
                s_x[(rh * 4 + j) * ROWP + c] = elu1(sum2(acc[j]) + bb);
        } else if (tid >= 600) {
            int t2 = tid - 600;
#pragma unroll
            for (int i = 0; i < RPC; i++) {
                if (i < NR)
                    s_eo[i * ROWP + t2] =
                        __ldg(&g_eo[((size_t)(b0 + i) * TLEN + t) * 200 + t2]);
            }
        }
        __syncthreads();

        // ====== P2: 3 streams x 1 col x 4 rows, twinned lanes ===============
        float xz[4], xr[4], xh[4];   // x-side results (sgP==0 only)
        {
            const float* src = sgP ? pd : s_x;
            const float* srb = src + rhP * 4 * ROWP;
            ull a0[4], a1[4], a2[4];
#pragma unroll
            for (int j = 0; j < 4; j++) { a0[j] = 0; a1[j] = 0; a2[j] = 0; }
            ulonglong2 w0 = ldg2(wpP2);
            ulonglong2 w1 = ldg2(wpP2 + 10000);
            ulonglong2 w2 = ldg2(wpP2 + 20000);
            for (int kq = 0; kq < 50; kq++) {
                const int kn = (kq < 49) ? kq + 1 : 49;
                ulonglong2 n0 = ldg2(wpP2 + kn * 200);
                ulonglong2 n1 = ldg2(wpP2 + 10000 + kn * 200);
                ulonglong2 n2 = ldg2(wpP2 + 20000 + kn * 200);
#pragma unroll
                for (int j = 0; j < 4; j++) {
                    ulonglong2 v = lds2(srb + j * ROWP + 4 * kq);
                    a0[j] = fma2(v.x, w0.x, a0[j]);
                    a0[j] = fma2(v.y, w0.y, a0[j]);
                    a1[j] = fma2(v.x, w1.x, a1[j]);
                    a1[j] = fma2(v.y, w1.y, a1[j]);
                    a2[j] = fma2(v.x, w2.x, a2[j]);
                    a2[j] = fma2(v.y, w2.y, a2[j]);
                }
                w0 = n0; w1 = n1; w2 = n2;
            }
            if (sgP) {
#pragma unroll
                for (int j = 0; j < 4; j++) {
                    int row = rhP * 4 + j;
                    s_g[row * ROWP + cP]            = sum2(a0[j]) + s_gb[600 + cP];
                    s_g[1632 + row * ROWP + cP]     = sum2(a1[j]) + s_gb[800 + cP];
                    s_g[3264 + row * ROWP + cP]     = sum2(a2[j]) + s_gb[1000 + cP];
                }
            } else {
#pragma unroll
                for (int j = 0; j < 4; j++) {
                    xz[j] = sum2(a0[j]) + s_gb[cP];
                    xr[j] = sum2(a1[j]) + s_gb[200 + cP];
                    xh[j] = sum2(a2[j]) + s_gb[400 + cP];
                }
            }
        }
        __syncthreads();

        // ====== P3: gates, deter_n (x-side threads own it) ==================
        if (tid < 400) {
#pragma unroll
            for (int j = 0; j < 4; j++) {
                int row = rhP * 4 + j;
                int idx = row * ROWP + cP;
                float z  = sigmoid1(xz[j] + s_g[idx]);
                float rg = sigmoid1(xr[j] + s_g[1632 + idx]);
                float a  = xh[j] + rg * s_g[3264 + idx];
                float e2 = __expf(2.f * a);
                float th = 1.f - 2.f * rcpa(e2 + 1.f);
                float dn = z * pd[idx] + (1.f - z) * th;
                pn[idx] = dn;
                if (row < NR) {
                    float* orow = out + ((size_t)(b0 + row) * TLEN + t) * 580;
                    orow[90 + cP]  = dn;
                    orow[380 + cP] = dn;
                }
            }
        }
        __syncthreads();

        // ====== P4: x2 / xo, 1 col x 4 rows, twinned lanes ==================
        {
            const float* db = pn + rhP4 * 4 * ROWP;
            ull acc[4];
#pragma unroll
            for (int j = 0; j < 4; j++) acc[j] = 0ull;
            ulonglong2 w = ldg2(wpP4);
            for (int kq = 0; kq < 50; kq++) {
                const int kn = (kq < 49) ? kq + 1 : 49;
                ulonglong2 n = ldg2(wpP4 + kn * 200);
#pragma unroll
                for (int j = 0; j < 4; j++) {
                    ulonglong2 v = lds2(db + j * ROWP + 4 * kq);
                    acc[j] = fma2(v.x, w.x, acc[j]);
                    acc[j] = fma2(v.y, w.y, acc[j]);
                }
                w = n;
            }
            if (matP4 == 0) {
                float bb = s_b2[cP4];
#pragma unroll
                for (int j = 0; j < 4; j++) {
                    int row = rhP4 * 4 + j;
                    s_x[row * ROWP + cP4] = elu1(sum2(acc[j]) + bb);
                }
            } else {
#pragma unroll
                for (int j = 0; j < 4; j++) {
                    int row = rhP4 * 4 + j;
                    s_xo[row * ROWP + cP4] = elu1(sum2(acc[j]) + s_eo[row * ROWP + cP4]);
                }
            }
        }
        __syncthreads();

        // ====== P5: heads + samples fused (480 thr) + action prefetch =======
        if (tid < 480) {
            float nz = vP5 ? __ldg(nptr + (size_t)t * (BSZ * SDIM)) : 0.f;

            const float* srcr = (pP5 ? s_x : s_xo) + rP5 * ROWP;
            ull am = 0ull, as = 0ull;
            ulonglong2 m0 = ldg2(wmP5);
            ulonglong2 s0 = ldg2(wsP5);
            for (int kq = 0; kq < 50; kq++) {
                int kn = (kq < 49) ? kq + 1 : 49;
                ulonglong2 mn = ldg2(wmP5 + kn * 30);
                ulonglong2 sn = ldg2(wsP5 + kn * 30);
                ulonglong2 v = lds2(srcr + 4 * kq);
                am = fma2(v.x, m0.x, am);
                am = fma2(v.y, m0.y, am);
                as = fma2(v.x, s0.x, as);
                as = fma2(v.y, s0.y, as);
                m0 = mn; s0 = sn;
            }
            float mean = sum2(am) + s_hb[2 * pP5 * 30 + sP5];
            float sdev = softplus1(sum2(as) + s_hb[(2 * pP5 + 1) * 30 + sP5]);
            if (pP5) sdev += 0.1f;
            float stoch = mean + sdev * nz;

            if (vP5) {
                float* op = optr + (size_t)t * 580;
                op[0]  = mean;
                op[30] = sdev;
                op[60] = stoch;
                if (pP5 == 0) s_in[rP5 * INP + sP5] = stoch;  // posterior carry
            }
        } else if (tid >= 752 && t + 1 < TLEN) {
            int idx = tid - 752;
            int r = idx / 6, j = idx % 6;
            if (r < NR)
                s_in[r * INP + 30 + j] =
                    action[(size_t)(b0 + r) * (TLEN * ADIM) + (t + 1) * ADIM + j];
        }

        { float* tmp = pd; pd = pn; pn = tmp; }
        __syncthreads();
    }
}

// ---------------------------------------------------------------------------
// Launch
// ---------------------------------------------------------------------------
extern "C" void kernel_launch(void* const* d_in, const int* in_sizes, int n_in,
                              void* d_out, int out_size) {
    const float* embed       = (const float*)d_in[0];
    const float* action      = (const float*)d_in[1];
    const float* noise_prior = (const float*)d_in[2];
    const float* noise_post  = (const float*)d_in[3];
    const float* w_img1      = (const float*)d_in[4];
    const float* b_img1      = (const float*)d_in[5];
    const float* gru_w       = (const float*)d_in[6];
    const float* gru_u       = (const float*)d_in[7];
    const float* gru_b       = (const float*)d_in[8];
    const float* gru_rb      = (const float*)d_in[9];
    const float* w_img2      = (const float*)d_in[10];
    const float* b_img2      = (const float*)d_in[11];
    const float* w_imean     = (const float*)d_in[12];
    const float* b_imean     = (const float*)d_in[13];
    const float* w_istd      = (const float*)d_in[14];
    const float* b_istd      = (const float*)d_in[15];
    const float* w_obs1      = (const float*)d_in[16];
    const float* b_obs1      = (const float*)d_in[17];
    const float* w_omean     = (const float*)d_in[18];
    const float* b_omean     = (const float*)d_in[19];
    const float* w_ostd      = (const float*)d_in[20];
    const float* b_ostd      = (const float*)d_in[21];
    float* out = (float*)d_out;

    repack_kernel<<<(556000 + 255) / 256, 256>>>(w_img1, gru_w, gru_u, w_img2,
                                                 w_obs1, w_omean, w_ostd,
                                                 w_imean, w_istd);
    eo_gemm_kernel<<<BSZ * TLEN / 64, 320>>>(embed, b_obs1);
    rssm_recur_kernel<<<(BSZ + RPC - 1) / RPC, 800>>>(action, noise_prior, noise_post,
                                                      b_img1, gru_b, gru_rb, b_img2,
                                                      b_imean, b_istd, b_omean, b_ostd, out);
}